// round 15
// baseline (speedup 1.0000x reference)
#include <cuda_runtime.h>
#include <cuda_bf16.h>
#include <cstdint>

#define NN 50000
#define EE 800000
#define INF 16
#define HH 64
#define WSTR 72
#define ASTR 72

// ---------------- scratch (static device globals; no allocs) ----------------
__device__ float g_h[NN * HH];
__device__ float g_a1[NN];
__device__ float g_a2[NN];
__device__ int   g_cnt[NN];
__device__ int   g_off[NN + 1];
__device__ int   g_cur[NN];
__device__ int2  g_csr_sd[EE];    // (src, dst) in CSR order
__device__ int2  g_csr_sw[EE];    // (src, w-bits) in CSR order
__device__ int   g_bsum[64];
// bf16 hi/lo split copies (padded by 64 rows for tile overrun)
__device__ __nv_bfloat16 g_hn_hi[(NN + 64) * HH];
__device__ __nv_bfloat16 g_hn_lo[(NN + 64) * HH];
__device__ __nv_bfloat16 g_h_hi[(NN + 64) * HH];
__device__ __nv_bfloat16 g_h_lo[(NN + 64) * HH];
// pre-split W image for all layers: [layer][(split*2+mat)][192][WSTR]
__device__ __align__(16) __nv_bfloat16 g_Wsp[3 * 4 * 192 * WSTR];

__device__ __forceinline__ float sigm(float x) {
    return 1.0f / (1.0f + __expf(-x));
}
__device__ __forceinline__ float tanh_fast(float x) {
    return 2.0f / (1.0f + __expf(-2.0f * x)) - 1.0f;
}
__device__ __forceinline__ uint32_t pk2bf(__nv_bfloat16 a, __nv_bfloat16 b) {
    __nv_bfloat162 t; t.x = a; t.y = b;
    return *(uint32_t*)&t;
}

// ---------------- W pre-split (all 3 layers, once per call) ----------------
__global__ void k_wsplit(const float* __restrict__ Wih, const float* __restrict__ Whh) {
    int idx = blockIdx.x * 256 + threadIdx.x;
    if (idx >= 3 * 2 * 192 * 64) return;
    int l = idx / (2 * 192 * 64);
    int r = idx - l * (2 * 192 * 64);
    int m = r / (192 * 64);
    int rr = r - m * (192 * 64);
    int o = rr >> 6, k = rr & 63;
    const float* W = m ? Whh : Wih;
    float v = W[l * 192 * 64 + rr];
    __nv_bfloat16 hi = __float2bfloat16(v);
    __nv_bfloat16 lo = __float2bfloat16(v - __bfloat162float(hi));
    size_t base = (size_t)l * 4 * 192 * WSTR;
    g_Wsp[base + ((size_t)(0 * 2 + m) * 192 + o) * WSTR + k] = hi;
    g_Wsp[base + ((size_t)(1 * 2 + m) * 192 + o) * WSTR + k] = lo;
}

// ---------------- CSR build ----------------
__global__ void k_zero(int n4) {
    int i = blockIdx.x * blockDim.x + threadIdx.x;
    if (i < n4) ((int4*)g_cnt)[i] = make_int4(0, 0, 0, 0);
}

__global__ void k_count(const int* __restrict__ dst, int e) {
    int i = blockIdx.x * blockDim.x + threadIdx.x;
    if (i < e) atomicAdd(&g_cnt[dst[i]], 1);
}

__global__ void k_scan1(int n) {
    __shared__ int wsum[32];
    int t = threadIdx.x;
    int i = blockIdx.x * 1024 + t;
    int v = (i < n) ? g_cnt[i] : 0;
    int x = v;
    #pragma unroll
    for (int d = 1; d < 32; d <<= 1) {
        int y = __shfl_up_sync(0xffffffffu, x, d);
        if ((t & 31) >= d) x += y;
    }
    if ((t & 31) == 31) wsum[t >> 5] = x;
    __syncthreads();
    if (t < 32) {
        int y = wsum[t];
        #pragma unroll
        for (int d = 1; d < 32; d <<= 1) {
            int z = __shfl_up_sync(0xffffffffu, y, d);
            if (t >= d) y += z;
        }
        wsum[t] = y;
    }
    __syncthreads();
    int excl = ((t >> 5) ? wsum[(t >> 5) - 1] : 0) + (x - v);
    if (i < n) g_off[i] = excl;
    if (t == 1023) g_bsum[blockIdx.x] = excl + v;
}

// scan3 with scan2 fused in: every block locally scans the <=64 block sums.
__global__ void k_scan3(int nb, int n) {
    __shared__ int sbs[64];
    __shared__ int w0tot;
    int t = threadIdx.x;
    if (t < 64) {
        int v = (t < nb) ? g_bsum[t] : 0;
        int x = v;
        #pragma unroll
        for (int d = 1; d < 32; d <<= 1) {
            int y = __shfl_up_sync(0xffffffffu, x, d);
            if ((t & 31) >= d) x += y;
        }
        if (t == 31) w0tot = x;
        sbs[t] = x - v;
    }
    __syncthreads();
    if (t >= 32 && t < 64) sbs[t] += w0tot;
    __syncthreads();
    int i = blockIdx.x * 1024 + t;
    if (i < n) {
        int o = g_off[i] + sbs[blockIdx.x];
        g_off[i] = o;
        g_cur[i] = o;
    }
    if (blockIdx.x == 0 && t == nb - 1) g_off[n] = sbs[t] + g_bsum[t];
}

__global__ void k_fill(const int* __restrict__ src, const int* __restrict__ dst, int e) {
    int i = blockIdx.x * blockDim.x + threadIdx.x;
    if (i < e) {
        int s = src[i], d = dst[i];
        int p = atomicAdd(&g_cur[d], 1);
        g_csr_sd[p] = make_int2(s, d);
    }
}

// ---------------- per-edge weights in CSR order (fully parallel) -------------
__global__ void k_w(const float* __restrict__ be, int e) {
    int j = blockIdx.x * 256 + threadIdx.x;
    if (j < e) {
        int2 sd = __ldg(&g_csr_sd[j]);
        float w = sigm(__ldg(&g_a1[sd.x]) + __ldg(&g_a2[sd.y]) + be[0]);
        g_csr_sw[j] = make_int2(sd.x, __float_as_int(w));
    }
}

// ---------------- input linear + bf16 split + fused layer-0 dots -------------
__global__ void k_input(const float* __restrict__ feat, const float* __restrict__ Win,
                        const float* __restrict__ bin, const float* __restrict__ We, int n) {
    __shared__ float sw[INF * HH];
    __shared__ float sb[HH];
    __shared__ float swe[128];
    __shared__ float wsum[8][2];
    int tid = threadIdx.x;
    for (int i = tid; i < INF * HH; i += 256) sw[i] = Win[i];
    if (tid < HH) sb[tid] = bin[tid];
    if (tid >= 128 && tid < 256) swe[tid - 128] = We[tid - 128];
    __syncthreads();
    int idx = blockIdx.x * 256 + tid;
    float p1 = 0.f, p2 = 0.f;
    if (idx < n * HH) {
        int node = idx >> 6, f = idx & 63;
        float acc = sb[f];
        const float* fr = feat + node * INF;
        #pragma unroll
        for (int i = 0; i < INF; i++) acc = fmaf(fr[i], sw[i * HH + f], acc);
        g_h[idx] = acc;
        __nv_bfloat16 hi = __float2bfloat16(acc);
        g_h_hi[idx] = hi;
        g_h_lo[idx] = __float2bfloat16(acc - __bfloat162float(hi));
        p1 = acc * swe[f];
        p2 = acc * swe[64 + f];
    }
    #pragma unroll
    for (int d = 16; d; d >>= 1) {
        p1 += __shfl_xor_sync(0xffffffffu, p1, d);
        p2 += __shfl_xor_sync(0xffffffffu, p2, d);
    }
    int wid = tid >> 5;
    if ((tid & 31) == 0) { wsum[wid][0] = p1; wsum[wid][1] = p2; }
    __syncthreads();
    if (tid < 4) {
        int gn = blockIdx.x * 4 + tid;
        if (gn < n) {
            g_a1[gn] = wsum[2 * tid][0] + wsum[2 * tid + 1][0];
            g_a2[gn] = wsum[2 * tid][1] + wsum[2 * tid + 1][1];
        }
    }
}

// ---------------- aggregation: pure FMA loop over precomputed (src,w) --------
__global__ void k_agg(int n) {
    int v = blockIdx.x * 8 + (threadIdx.x >> 5);
    int lane = threadIdx.x & 31;
    if (v >= n) return;
    int j0 = g_off[v], j1 = g_off[v + 1];
    int half = lane >> 4, hl = lane & 15;
    float4 acc0 = make_float4(0.f, 0.f, 0.f, 0.f);
    float4 acc1 = make_float4(0.f, 0.f, 0.f, 0.f);
    int j = j0 + half;
    for (; j + 2 < j1; j += 4) {
        int2 sw0 = __ldg(&g_csr_sw[j]);
        int2 sw1 = __ldg(&g_csr_sw[j + 2]);
        float w0 = __int_as_float(sw0.y);
        float w1 = __int_as_float(sw1.y);
        float4 h0 = *(const float4*)&g_h[(size_t)sw0.x * HH + hl * 4];
        float4 h1 = *(const float4*)&g_h[(size_t)sw1.x * HH + hl * 4];
        acc0.x = fmaf(w0, h0.x, acc0.x); acc0.y = fmaf(w0, h0.y, acc0.y);
        acc0.z = fmaf(w0, h0.z, acc0.z); acc0.w = fmaf(w0, h0.w, acc0.w);
        acc1.x = fmaf(w1, h1.x, acc1.x); acc1.y = fmaf(w1, h1.y, acc1.y);
        acc1.z = fmaf(w1, h1.z, acc1.z); acc1.w = fmaf(w1, h1.w, acc1.w);
    }
    if (j < j1) {
        int2 sw = __ldg(&g_csr_sw[j]);
        float w = __int_as_float(sw.y);
        float4 hv = *(const float4*)&g_h[(size_t)sw.x * HH + hl * 4];
        acc0.x = fmaf(w, hv.x, acc0.x); acc0.y = fmaf(w, hv.y, acc0.y);
        acc0.z = fmaf(w, hv.z, acc0.z); acc0.w = fmaf(w, hv.w, acc0.w);
    }
    acc0.x += acc1.x; acc0.y += acc1.y; acc0.z += acc1.z; acc0.w += acc1.w;
    acc0.x += __shfl_xor_sync(0xffffffffu, acc0.x, 16);
    acc0.y += __shfl_xor_sync(0xffffffffu, acc0.y, 16);
    acc0.z += __shfl_xor_sync(0xffffffffu, acc0.z, 16);
    acc0.w += __shfl_xor_sync(0xffffffffu, acc0.w, 16);
    if (half == 0) {
        __nv_bfloat16 hx = __float2bfloat16(acc0.x);
        __nv_bfloat16 hy = __float2bfloat16(acc0.y);
        __nv_bfloat16 hz = __float2bfloat16(acc0.z);
        __nv_bfloat16 hw = __float2bfloat16(acc0.w);
        __nv_bfloat16 lx = __float2bfloat16(acc0.x - __bfloat162float(hx));
        __nv_bfloat16 ly = __float2bfloat16(acc0.y - __bfloat162float(hy));
        __nv_bfloat16 lz = __float2bfloat16(acc0.z - __bfloat162float(hz));
        __nv_bfloat16 lw = __float2bfloat16(acc0.w - __bfloat162float(hw));
        size_t o = (size_t)v * HH + hl * 4;
        *(uint2*)&g_hn_hi[o] = make_uint2(pk2bf(hx, hy), pk2bf(hz, hw));
        *(uint2*)&g_hn_lo[o] = make_uint2(pk2bf(lx, ly), pk2bf(lz, lw));
    }
}

// ---------------- tensor-core GRU: cp.async W + A, ldmatrix, reg epilogue ----
#define ACH (64 * ASTR * 2)                // bytes per A chunk
#define ABUF_BYTES (4 * ACH)               // 36864 per buffer
#define SW_OFF   0                         // 110592 B
#define SA0_OFF  110592
#define SA1_OFF  (SA0_OFF + ABUF_BYTES)    // 147456
#define SD_OFF   (SA1_OFF + ABUF_BYTES)    // 184320
#define SB_OFF   (SD_OFF + 4096)           // 188416
#define SWE_OFF  (SB_OFF + 1536)           // 189952
#define SMEM_BYTES (SWE_OFF + 512)         // 190464
#define W_CHUNKS (4 * 192 * WSTR * 2 / 16) // 6912 16B chunks

#define MMA_BF16(acc, a, b)                                                     \
    asm volatile(                                                               \
        "mma.sync.aligned.m16n8k16.row.col.f32.bf16.bf16.f32 "                  \
        "{%0,%1,%2,%3},{%4,%5,%6,%7},{%8,%9},{%0,%1,%2,%3};"                    \
        : "+f"(acc[0]), "+f"(acc[1]), "+f"(acc[2]), "+f"(acc[3])                \
        : "r"(a[0]), "r"(a[1]), "r"(a[2]), "r"(a[3]), "r"(b[0]), "r"(b[1]))

#define LDSM4(r, addr)                                                          \
    asm volatile("ldmatrix.sync.aligned.m8n8.x4.shared.b16 {%0,%1,%2,%3}, [%4];"\
        : "=r"(r[0]), "=r"(r[1]), "=r"(r[2]), "=r"(r[3]) : "r"(addr))

#define LDSM2(r, addr)                                                          \
    asm volatile("ldmatrix.sync.aligned.m8n8.x2.shared.b16 {%0,%1}, [%2];"      \
        : "=r"(r[0]), "=r"(r[1]) : "r"(addr))

#define CP_ASYNC16(saddr, gptr)                                                 \
    asm volatile("cp.async.cg.shared.global [%0], [%1], 16;"                    \
        :: "r"(saddr), "l"(gptr) : "memory")
#define CP_COMMIT()  asm volatile("cp.async.commit_group;" ::: "memory")
#define CP_WAIT0()   asm volatile("cp.async.wait_group 0;" ::: "memory")

__global__ void __launch_bounds__(512, 1)
k_gru(int layer,
      const float* __restrict__ bih, const float* __restrict__ bhh,
      const float* __restrict__ Wd, int n) {
    extern __shared__ char smem[];
    float* sd  = (float*)(smem + SD_OFF);
    float* sB  = (float*)(smem + SB_OFF);
    float* sWe = (float*)(smem + SWE_OFF);

    int tid  = threadIdx.x;
    int w    = tid >> 5, lane = tid & 31;
    int gi   = lane >> 2, tc = lane & 3;
    int fb   = (w & 7) * 8;
    int mh   = w >> 3;
    int wslot = w & 7;
    uint32_t sb32 = (uint32_t)__cvta_generic_to_shared(smem);

    // ---- stage W via vectorized cp.async from pre-split global image ----
    const uint4* Wg = (const uint4*)(g_Wsp + (size_t)layer * 4 * 192 * WSTR);
    for (int c = tid; c < W_CHUNKS; c += 512)
        CP_ASYNC16(sb32 + SW_OFF + (uint32_t)(c * 16), (const void*)(Wg + c));

    for (int idx = tid; idx < 384; idx += 512)
        sB[idx] = (idx < 192) ? bih[idx] : bhh[idx - 192];
    if (tid < 128) sWe[tid] = Wd[tid];

    int srow = tid >> 3, sseg = tid & 7;
    uint32_t sdst = (uint32_t)(srow * ASTR * 2 + sseg * 16);
    uint32_t bufB[2] = { sb32 + SA0_OFF, sb32 + SA1_OFF };
    char* bufP[2] = { smem + SA0_OFF, smem + SA1_OFF };

    int ntiles = (n + 63) / 64;
    int first = blockIdx.x;

    if (first < ntiles) {
        size_t go = (size_t)(first * 64 + srow) * HH + sseg * 8;
        CP_ASYNC16(bufB[0] + 0 * ACH + sdst, (const void*)(g_hn_hi + go));
        CP_ASYNC16(bufB[0] + 1 * ACH + sdst, (const void*)(g_hn_lo + go));
        CP_ASYNC16(bufB[0] + 2 * ACH + sdst, (const void*)(g_h_hi + go));
        CP_ASYNC16(bufB[0] + 3 * ACH + sdst, (const void*)(g_h_lo + go));
    }
    CP_COMMIT();
    CP_WAIT0();
    __syncthreads();

    int c0 = fb + tc * 2;
    float we1a = sWe[c0], we1b = sWe[c0 + 1];
    float we2a = sWe[64 + c0], we2b = sWe[64 + c0 + 1];
    float bI[3][2], bH[3][2];
    #pragma unroll
    for (int g = 0; g < 3; g++) {
        bI[g][0] = sB[g * 64 + c0];       bI[g][1] = sB[g * 64 + c0 + 1];
        bH[g][0] = sB[192 + g * 64 + c0]; bH[g][1] = sB[192 + g * 64 + c0 + 1];
    }

    uint32_t aoff = ((lane & 15) * ASTR + (lane >> 4) * 8) * 2 + (uint32_t)(mh * 32 * ASTR * 2);
    uint32_t boff = ((lane & 7) * WSTR + ((lane >> 3) & 1) * 8) * 2;
    uint32_t bBase[6][2];
    #pragma unroll
    for (int g = 0; g < 6; g++) {
        int m = (g < 3) ? 0 : 1;
        int gc = g - m * 3;
        #pragma unroll
        for (int s = 0; s < 2; s++)
            bBase[g][s] = sb32 + SW_OFF +
                (uint32_t)((((s * 2 + m) * 192 + gc * 64 + fb) * WSTR) * 2) + boff;
    }

    int parity = 0;
    for (int tile = first; tile < ntiles; tile += gridDim.x) {
        int n0 = tile * 64;
        uint32_t cur = bufB[parity];
        char* curp = bufP[parity];

        int nxt = tile + gridDim.x;
        if (nxt < ntiles) {
            uint32_t dst = bufB[parity ^ 1];
            size_t go = (size_t)(nxt * 64 + srow) * HH + sseg * 8;
            CP_ASYNC16(dst + 0 * ACH + sdst, (const void*)(g_hn_hi + go));
            CP_ASYNC16(dst + 1 * ACH + sdst, (const void*)(g_hn_lo + go));
            CP_ASYNC16(dst + 2 * ACH + sdst, (const void*)(g_h_hi + go));
            CP_ASYNC16(dst + 3 * ACH + sdst, (const void*)(g_h_lo + go));
        }
        CP_COMMIT();

        uint32_t aB0 = cur + 0 * ACH + aoff;
        uint32_t aB1 = cur + 1 * ACH + aoff;
        uint32_t aB2 = cur + 2 * ACH + aoff;
        uint32_t aB3 = cur + 3 * ACH + aoff;

        float acc[12][4];
        #pragma unroll
        for (int i = 0; i < 12; i++) {
            acc[i][0] = 0.f; acc[i][1] = 0.f; acc[i][2] = 0.f; acc[i][3] = 0.f;
        }

        #pragma unroll
        for (int kc = 0; kc < 64; kc += 16) {
            uint32_t kb = kc * 2;
            uint32_t AnH[2][4], AnL[2][4], AhH[2][4], AhL[2][4];
            #pragma unroll
            for (int i = 0; i < 2; i++) {
                uint32_t off = (uint32_t)(i * 16 * ASTR * 2) + kb;
                LDSM4(AnH[i], aB0 + off);
                LDSM4(AnL[i], aB1 + off);
                LDSM4(AhH[i], aB2 + off);
                LDSM4(AhL[i], aB3 + off);
            }
            #pragma unroll
            for (int g = 0; g < 6; g++) {
                uint32_t Bh[2], Bl[2];
                LDSM2(Bh, bBase[g][0] + kb);
                LDSM2(Bl, bBase[g][1] + kb);
                #pragma unroll
                for (int i = 0; i < 2; i++) {
                    const uint32_t* ah = (g < 3) ? AnH[i] : AhH[i];
                    const uint32_t* al = (g < 3) ? AnL[i] : AhL[i];
                    MMA_BF16(acc[g * 2 + i], ah, Bh);
                    MMA_BF16(acc[g * 2 + i], ah, Bl);
                    MMA_BF16(acc[g * 2 + i], al, Bh);
                }
            }
        }

        // ---- register GRU epilogue: hold reconstructed from smem hi+lo ----
        #pragma unroll
        for (int i = 0; i < 2; i++) {
            #pragma unroll
            for (int hlf = 0; hlf < 2; hlf++) {
                int row = mh * 32 + i * 16 + gi + hlf * 8;
                int gn = n0 + row;
                float P1 = 0.f, P2 = 0.f;
                if (gn < n) {
                    int a = hlf * 2;
                    uint32_t hoff = (uint32_t)((row * ASTR + c0) * 2);
                    __nv_bfloat162 hhi = *(__nv_bfloat162*)(curp + 2 * ACH + hoff);
                    __nv_bfloat162 hlo = *(__nv_bfloat162*)(curp + 3 * ACH + hoff);
                    float2 hold;
                    hold.x = __bfloat162float(hhi.x) + __bfloat162float(hlo.x);
                    hold.y = __bfloat162float(hhi.y) + __bfloat162float(hlo.y);
                    float ho[2];
                    #pragma unroll
                    for (int q = 0; q < 2; q++) {
                        float ir  = acc[0 * 2 + i][a + q] + bI[0][q];
                        float iz  = acc[1 * 2 + i][a + q] + bI[1][q];
                        float in_ = acc[2 * 2 + i][a + q] + bI[2][q];
                        float hr  = acc[3 * 2 + i][a + q] + bH[0][q];
                        float hz  = acc[4 * 2 + i][a + q] + bH[1][q];
                        float hn  = acc[5 * 2 + i][a + q] + bH[2][q];
                        float hv  = q ? hold.y : hold.x;
                        float r = sigm(ir + hr);
                        float z = sigm(iz + hz);
                        float nn_ = tanh_fast(fmaf(r, hn, in_));
                        ho[q] = fmaf(1.f - z, nn_, z * hv);
                    }
                    *(float2*)&g_h[(size_t)gn * HH + c0] = make_float2(ho[0], ho[1]);
                    __nv_bfloat16 h0 = __float2bfloat16(ho[0]);
                    __nv_bfloat16 h1 = __float2bfloat16(ho[1]);
                    __nv_bfloat16 l0 = __float2bfloat16(ho[0] - __bfloat162float(h0));
                    __nv_bfloat16 l1 = __float2bfloat16(ho[1] - __bfloat162float(h1));
                    *(uint32_t*)&g_h_hi[(size_t)gn * HH + c0] = pk2bf(h0, h1);
                    *(uint32_t*)&g_h_lo[(size_t)gn * HH + c0] = pk2bf(l0, l1);
                    P1 = ho[0] * we1a + ho[1] * we1b;
                    P2 = ho[0] * we2a + ho[1] * we2b;
                }
                P1 += __shfl_xor_sync(0xffffffffu, P1, 1);
                P1 += __shfl_xor_sync(0xffffffffu, P1, 2);
                P2 += __shfl_xor_sync(0xffffffffu, P2, 1);
                P2 += __shfl_xor_sync(0xffffffffu, P2, 2);
                if (tc == 0) {
                    sd[(0 * 64 + row) * 8 + wslot] = P1;
                    sd[(1 * 64 + row) * 8 + wslot] = P2;
                }
            }
        }
        __syncthreads();

        if (tid < 128) {
            int p = tid >> 6, row = tid & 63;
            int gn = n0 + row;
            if (gn < n) {
                const float* s = sd + (p * 64 + row) * 8;
                float v = ((s[0] + s[1]) + (s[2] + s[3])) + ((s[4] + s[5]) + (s[6] + s[7]));
                if (p == 0) g_a1[gn] = v; else g_a2[gn] = v;
            }
        }
        CP_WAIT0();
        __syncthreads();
        parity ^= 1;
    }
}

// ---------------- final edge predictor ----------------
__global__ void k_pred(const int* __restrict__ src, const int* __restrict__ dst,
                       const float* __restrict__ bp, float* __restrict__ out, int e) {
    int i = blockIdx.x * blockDim.x + threadIdx.x;
    if (i < e) out[i] = g_a1[src[i]] + g_a2[dst[i]] + bp[0];
}

// ---------------- launch ----------------
extern "C" void kernel_launch(void* const* d_in, const int* in_sizes, int n_in,
                              void* d_out, int out_size) {
    const float* feat = (const float*)d_in[0];
    const int*   src  = (const int*)d_in[1];
    const int*   dst  = (const int*)d_in[2];
    const float* Win  = (const float*)d_in[3];
    const float* bin  = (const float*)d_in[4];
    const float* We   = (const float*)d_in[5];
    const float* be   = (const float*)d_in[6];
    const float* Wih  = (const float*)d_in[7];
    const float* Whh  = (const float*)d_in[8];
    const float* bih  = (const float*)d_in[9];
    const float* bhh  = (const float*)d_in[10];
    const float* Wp   = (const float*)d_in[11];
    const float* bp   = (const float*)d_in[12];
    float* out = (float*)d_out;

    int n = in_sizes[0] / INF;   // 50000
    int e = in_sizes[1];         // 800000
    int nb = (n + 1023) / 1024;  // scan blocks

    cudaFuncSetAttribute(k_gru, cudaFuncAttributeMaxDynamicSharedMemorySize, SMEM_BYTES);

    k_wsplit<<<(3 * 2 * 192 * 64 + 255) / 256, 256>>>(Wih, Whh);
    // CSR build
    k_zero<<<(n / 4 + 255) / 256, 256>>>(n / 4);
    k_count<<<(e + 255) / 256, 256>>>(dst, e);
    k_scan1<<<nb, 1024>>>(n);
    k_scan3<<<nb, 1024>>>(nb, n);
    k_fill<<<(e + 255) / 256, 256>>>(src, dst, e);

    k_input<<<(n * HH + 255) / 256, 256>>>(feat, Win, bin, We, n);

    for (int l = 0; l < 3; l++) {
        k_w<<<(e + 255) / 256, 256>>>(be, e);
        k_agg<<<(n + 7) / 8, 256>>>(n);
        const float* Wd = (l == 2) ? Wp : We;
        k_gru<<<148, 512, SMEM_BYTES>>>(l, bih + l * 192, bhh + l * 192, Wd, n);
    }

    k_pred<<<(e + 255) / 256, 256>>>(src, dst, bp, out, e);
}

// round 17
// speedup vs baseline: 1.0160x; 1.0160x over previous
#include <cuda_runtime.h>
#include <cuda_bf16.h>
#include <cstdint>

#define NN 50000
#define EE 800000
#define INF 16
#define HH 64
#define WSTR 72
#define ASTR 72

// ---------------- scratch (static device globals; no allocs) ----------------
__device__ float g_h[NN * HH];
__device__ float g_a1[NN];
__device__ float g_a2[NN];
__device__ int   g_cnt[NN];        // zero-initialized at load; k_scan1 re-zeroes
__device__ int   g_off[NN + 1];
__device__ int   g_cur[NN];
__device__ int2  g_csr_sd[EE];     // (src, dst) in CSR order
__device__ int2  g_csr_sw[EE];     // (src, w-bits) in CSR order
__device__ int   g_bsum[64];
// bf16 hi/lo split copies (padded by 64 rows for tile overrun)
__device__ __nv_bfloat16 g_hn_hi[(NN + 64) * HH];
__device__ __nv_bfloat16 g_hn_lo[(NN + 64) * HH];
__device__ __nv_bfloat16 g_h_hi[(NN + 64) * HH];
__device__ __nv_bfloat16 g_h_lo[(NN + 64) * HH];
// pre-split W image for all layers: [layer][(split*2+mat)][192][WSTR]
__device__ __align__(16) __nv_bfloat16 g_Wsp[3 * 4 * 192 * WSTR];

__device__ __forceinline__ float sigm(float x) {
    return 1.0f / (1.0f + __expf(-x));
}
__device__ __forceinline__ float tanh_fast(float x) {
    return 2.0f / (1.0f + __expf(-2.0f * x)) - 1.0f;
}
__device__ __forceinline__ uint32_t pk2bf(__nv_bfloat16 a, __nv_bfloat16 b) {
    __nv_bfloat162 t; t.x = a; t.y = b;
    return *(uint32_t*)&t;
}

// ---------------- W pre-split (all 3 layers, once per call) ----------------
__global__ void k_wsplit(const float* __restrict__ Wih, const float* __restrict__ Whh) {
    int idx = blockIdx.x * 256 + threadIdx.x;
    if (idx >= 3 * 2 * 192 * 64) return;
    int l = idx / (2 * 192 * 64);
    int r = idx - l * (2 * 192 * 64);
    int m = r / (192 * 64);
    int rr = r - m * (192 * 64);
    int o = rr >> 6, k = rr & 63;
    const float* W = m ? Whh : Wih;
    float v = W[l * 192 * 64 + rr];
    __nv_bfloat16 hi = __float2bfloat16(v);
    __nv_bfloat16 lo = __float2bfloat16(v - __bfloat162float(hi));
    size_t base = (size_t)l * 4 * 192 * WSTR;
    g_Wsp[base + ((size_t)(0 * 2 + m) * 192 + o) * WSTR + k] = hi;
    g_Wsp[base + ((size_t)(1 * 2 + m) * 192 + o) * WSTR + k] = lo;
}

// ---------------- CSR build ----------------
// count: 4 edges per thread (e divisible by 4)
__global__ void k_count(const int4* __restrict__ dst4, int e4) {
    int i = blockIdx.x * blockDim.x + threadIdx.x;
    if (i < e4) {
        int4 d = __ldg(&dst4[i]);
        atomicAdd(&g_cnt[d.x], 1);
        atomicAdd(&g_cnt[d.y], 1);
        atomicAdd(&g_cnt[d.z], 1);
        atomicAdd(&g_cnt[d.w], 1);
    }
}

// scan1: per-block exclusive scan of g_cnt -> g_off; re-zeroes g_cnt for the
// next graph replay (module-load zero-init covers the very first call).
__global__ void k_scan1(int n) {
    __shared__ int wsum[32];
    int t = threadIdx.x;
    int i = blockIdx.x * 1024 + t;
    int v = (i < n) ? g_cnt[i] : 0;
    int x = v;
    #pragma unroll
    for (int d = 1; d < 32; d <<= 1) {
        int y = __shfl_up_sync(0xffffffffu, x, d);
        if ((t & 31) >= d) x += y;
    }
    if ((t & 31) == 31) wsum[t >> 5] = x;
    __syncthreads();
    if (t < 32) {
        int y = wsum[t];
        #pragma unroll
        for (int d = 1; d < 32; d <<= 1) {
            int z = __shfl_up_sync(0xffffffffu, y, d);
            if (t >= d) y += z;
        }
        wsum[t] = y;
    }
    __syncthreads();
    int excl = ((t >> 5) ? wsum[(t >> 5) - 1] : 0) + (x - v);
    if (i < n) { g_off[i] = excl; g_cnt[i] = 0; }
    if (t == 1023) g_bsum[blockIdx.x] = excl + v;
}

// scan3 with scan2 fused: every block locally scans the <=64 block sums.
__global__ void k_scan3(int nb, int n) {
    __shared__ int sbs[64];
    __shared__ int w0tot;
    int t = threadIdx.x;
    if (t < 64) {
        int v = (t < nb) ? g_bsum[t] : 0;
        int x = v;
        #pragma unroll
        for (int d = 1; d < 32; d <<= 1) {
            int y = __shfl_up_sync(0xffffffffu, x, d);
            if ((t & 31) >= d) x += y;
        }
        if (t == 31) w0tot = x;
        sbs[t] = x - v;
    }
    __syncthreads();
    if (t >= 32 && t < 64) sbs[t] += w0tot;
    __syncthreads();
    int i = blockIdx.x * 1024 + t;
    if (i < n) {
        int o = g_off[i] + sbs[blockIdx.x];
        g_off[i] = o;
        g_cur[i] = o;
    }
    if (blockIdx.x == 0 && t == nb - 1) g_off[n] = sbs[t] + g_bsum[t];
}

__global__ void k_fill(const int* __restrict__ src, const int* __restrict__ dst, int e) {
    int i = blockIdx.x * blockDim.x + threadIdx.x;
    if (i < e) {
        int s = src[i], d = dst[i];
        int p = atomicAdd(&g_cur[d], 1);
        g_csr_sd[p] = make_int2(s, d);
    }
}

// ---------------- per-edge weights in CSR order (2 edges/thread) -------------
__global__ void k_w(const float* __restrict__ be, int e2) {
    int j = blockIdx.x * 256 + threadIdx.x;
    if (j < e2) {
        int4 sd = __ldg(&((const int4*)g_csr_sd)[j]);
        float b = be[0];
        float w0 = sigm(__ldg(&g_a1[sd.x]) + __ldg(&g_a2[sd.y]) + b);
        float w1 = sigm(__ldg(&g_a1[sd.z]) + __ldg(&g_a2[sd.w]) + b);
        ((int4*)g_csr_sw)[j] = make_int4(sd.x, __float_as_int(w0),
                                         sd.z, __float_as_int(w1));
    }
}

// ---------------- input linear + bf16 split + fused layer-0 dots -------------
__global__ void k_input(const float* __restrict__ feat, const float* __restrict__ Win,
                        const float* __restrict__ bin, const float* __restrict__ We, int n) {
    __shared__ float sw[INF * HH];
    __shared__ float sb[HH];
    __shared__ float swe[128];
    __shared__ float wsum[8][2];
    int tid = threadIdx.x;
    for (int i = tid; i < INF * HH; i += 256) sw[i] = Win[i];
    if (tid < HH) sb[tid] = bin[tid];
    if (tid >= 128 && tid < 256) swe[tid - 128] = We[tid - 128];
    __syncthreads();
    int idx = blockIdx.x * 256 + tid;
    float p1 = 0.f, p2 = 0.f;
    if (idx < n * HH) {
        int node = idx >> 6, f = idx & 63;
        float acc = sb[f];
        const float* fr = feat + node * INF;
        #pragma unroll
        for (int i = 0; i < INF; i++) acc = fmaf(fr[i], sw[i * HH + f], acc);
        g_h[idx] = acc;
        __nv_bfloat16 hi = __float2bfloat16(acc);
        g_h_hi[idx] = hi;
        g_h_lo[idx] = __float2bfloat16(acc - __bfloat162float(hi));
        p1 = acc * swe[f];
        p2 = acc * swe[64 + f];
    }
    #pragma unroll
    for (int d = 16; d; d >>= 1) {
        p1 += __shfl_xor_sync(0xffffffffu, p1, d);
        p2 += __shfl_xor_sync(0xffffffffu, p2, d);
    }
    int wid = tid >> 5;
    if ((tid & 31) == 0) { wsum[wid][0] = p1; wsum[wid][1] = p2; }
    __syncthreads();
    if (tid < 4) {
        int gn = blockIdx.x * 4 + tid;
        if (gn < n) {
            g_a1[gn] = wsum[2 * tid][0] + wsum[2 * tid + 1][0];
            g_a2[gn] = wsum[2 * tid][1] + wsum[2 * tid + 1][1];
        }
    }
}

// ---------------- aggregation: pure FMA loop over precomputed (src,w) --------
__global__ void k_agg(int n) {
    int v = blockIdx.x * 8 + (threadIdx.x >> 5);
    int lane = threadIdx.x & 31;
    if (v >= n) return;
    int j0 = g_off[v], j1 = g_off[v + 1];
    int half = lane >> 4, hl = lane & 15;
    float4 acc0 = make_float4(0.f, 0.f, 0.f, 0.f);
    float4 acc1 = make_float4(0.f, 0.f, 0.f, 0.f);
    int j = j0 + half;
    for (; j + 2 < j1; j += 4) {
        int2 sw0 = __ldg(&g_csr_sw[j]);
        int2 sw1 = __ldg(&g_csr_sw[j + 2]);
        float w0 = __int_as_float(sw0.y);
        float w1 = __int_as_float(sw1.y);
        float4 h0 = *(const float4*)&g_h[(size_t)sw0.x * HH + hl * 4];
        float4 h1 = *(const float4*)&g_h[(size_t)sw1.x * HH + hl * 4];
        acc0.x = fmaf(w0, h0.x, acc0.x); acc0.y = fmaf(w0, h0.y, acc0.y);
        acc0.z = fmaf(w0, h0.z, acc0.z); acc0.w = fmaf(w0, h0.w, acc0.w);
        acc1.x = fmaf(w1, h1.x, acc1.x); acc1.y = fmaf(w1, h1.y, acc1.y);
        acc1.z = fmaf(w1, h1.z, acc1.z); acc1.w = fmaf(w1, h1.w, acc1.w);
    }
    if (j < j1) {
        int2 sw = __ldg(&g_csr_sw[j]);
        float w = __int_as_float(sw.y);
        float4 hv = *(const float4*)&g_h[(size_t)sw.x * HH + hl * 4];
        acc0.x = fmaf(w, hv.x, acc0.x); acc0.y = fmaf(w, hv.y, acc0.y);
        acc0.z = fmaf(w, hv.z, acc0.z); acc0.w = fmaf(w, hv.w, acc0.w);
    }
    acc0.x += acc1.x; acc0.y += acc1.y; acc0.z += acc1.z; acc0.w += acc1.w;
    acc0.x += __shfl_xor_sync(0xffffffffu, acc0.x, 16);
    acc0.y += __shfl_xor_sync(0xffffffffu, acc0.y, 16);
    acc0.z += __shfl_xor_sync(0xffffffffu, acc0.z, 16);
    acc0.w += __shfl_xor_sync(0xffffffffu, acc0.w, 16);
    if (half == 0) {
        __nv_bfloat16 hx = __float2bfloat16(acc0.x);
        __nv_bfloat16 hy = __float2bfloat16(acc0.y);
        __nv_bfloat16 hz = __float2bfloat16(acc0.z);
        __nv_bfloat16 hw = __float2bfloat16(acc0.w);
        __nv_bfloat16 lx = __float2bfloat16(acc0.x - __bfloat162float(hx));
        __nv_bfloat16 ly = __float2bfloat16(acc0.y - __bfloat162float(hy));
        __nv_bfloat16 lz = __float2bfloat16(acc0.z - __bfloat162float(hz));
        __nv_bfloat16 lw = __float2bfloat16(acc0.w - __bfloat162float(hw));
        size_t o = (size_t)v * HH + hl * 4;
        *(uint2*)&g_hn_hi[o] = make_uint2(pk2bf(hx, hy), pk2bf(hz, hw));
        *(uint2*)&g_hn_lo[o] = make_uint2(pk2bf(lx, ly), pk2bf(lz, lw));
    }
}

// ---------------- tensor-core GRU: cp.async W + A, ldmatrix, reg epilogue ----
#define ACH (64 * ASTR * 2)
#define ABUF_BYTES (4 * ACH)
#define SW_OFF   0
#define SA0_OFF  110592
#define SA1_OFF  (SA0_OFF + ABUF_BYTES)
#define SD_OFF   (SA1_OFF + ABUF_BYTES)
#define SB_OFF   (SD_OFF + 4096)
#define SWE_OFF  (SB_OFF + 1536)
#define SMEM_BYTES (SWE_OFF + 512)
#define W_CHUNKS (4 * 192 * WSTR * 2 / 16)

#define MMA_BF16(acc, a, b)                                                     \
    asm volatile(                                                               \
        "mma.sync.aligned.m16n8k16.row.col.f32.bf16.bf16.f32 "                  \
        "{%0,%1,%2,%3},{%4,%5,%6,%7},{%8,%9},{%0,%1,%2,%3};"                    \
        : "+f"(acc[0]), "+f"(acc[1]), "+f"(acc[2]), "+f"(acc[3])                \
        : "r"(a[0]), "r"(a[1]), "r"(a[2]), "r"(a[3]), "r"(b[0]), "r"(b[1]))

#define LDSM4(r, addr)                                                          \
    asm volatile("ldmatrix.sync.aligned.m8n8.x4.shared.b16 {%0,%1,%2,%3}, [%4];"\
        : "=r"(r[0]), "=r"(r[1]), "=r"(r[2]), "=r"(r[3]) : "r"(addr))

#define LDSM2(r, addr)                                                          \
    asm volatile("ldmatrix.sync.aligned.m8n8.x2.shared.b16 {%0,%1}, [%2];"      \
        : "=r"(r[0]), "=r"(r[1]) : "r"(addr))

#define CP_ASYNC16(saddr, gptr)                                                 \
    asm volatile("cp.async.cg.shared.global [%0], [%1], 16;"                    \
        :: "r"(saddr), "l"(gptr) : "memory")
#define CP_COMMIT()  asm volatile("cp.async.commit_group;" ::: "memory")
#define CP_WAIT0()   asm volatile("cp.async.wait_group 0;" ::: "memory")

__global__ void __launch_bounds__(512, 1)
k_gru(int layer,
      const float* __restrict__ bih, const float* __restrict__ bhh,
      const float* __restrict__ Wd, int n) {
    extern __shared__ char smem[];
    float* sd  = (float*)(smem + SD_OFF);
    float* sB  = (float*)(smem + SB_OFF);
    float* sWe = (float*)(smem + SWE_OFF);

    int tid  = threadIdx.x;
    int w    = tid >> 5, lane = tid & 31;
    int gi   = lane >> 2, tc = lane & 3;
    int fb   = (w & 7) * 8;
    int mh   = w >> 3;
    int wslot = w & 7;
    uint32_t sb32 = (uint32_t)__cvta_generic_to_shared(smem);

    const uint4* Wg = (const uint4*)(g_Wsp + (size_t)layer * 4 * 192 * WSTR);
    for (int c = tid; c < W_CHUNKS; c += 512)
        CP_ASYNC16(sb32 + SW_OFF + (uint32_t)(c * 16), (const void*)(Wg + c));

    for (int idx = tid; idx < 384; idx += 512)
        sB[idx] = (idx < 192) ? bih[idx] : bhh[idx - 192];
    if (tid < 128) sWe[tid] = Wd[tid];

    int srow = tid >> 3, sseg = tid & 7;
    uint32_t sdst = (uint32_t)(srow * ASTR * 2 + sseg * 16);
    uint32_t bufB[2] = { sb32 + SA0_OFF, sb32 + SA1_OFF };

    int ntiles = (n + 63) / 64;
    int first = blockIdx.x;

    if (first < ntiles) {
        size_t go = (size_t)(first * 64 + srow) * HH + sseg * 8;
        CP_ASYNC16(bufB[0] + 0 * ACH + sdst, (const void*)(g_hn_hi + go));
        CP_ASYNC16(bufB[0] + 1 * ACH + sdst, (const void*)(g_hn_lo + go));
        CP_ASYNC16(bufB[0] + 2 * ACH + sdst, (const void*)(g_h_hi + go));
        CP_ASYNC16(bufB[0] + 3 * ACH + sdst, (const void*)(g_h_lo + go));
    }
    CP_COMMIT();
    CP_WAIT0();
    __syncthreads();

    int c0 = fb + tc * 2;
    float we1a = sWe[c0], we1b = sWe[c0 + 1];
    float we2a = sWe[64 + c0], we2b = sWe[64 + c0 + 1];
    float bI[3][2], bH[3][2];
    #pragma unroll
    for (int g = 0; g < 3; g++) {
        bI[g][0] = sB[g * 64 + c0];       bI[g][1] = sB[g * 64 + c0 + 1];
        bH[g][0] = sB[192 + g * 64 + c0]; bH[g][1] = sB[192 + g * 64 + c0 + 1];
    }

    uint32_t aoff = ((lane & 15) * ASTR + (lane >> 4) * 8) * 2 + (uint32_t)(mh * 32 * ASTR * 2);
    uint32_t boff = ((lane & 7) * WSTR + ((lane >> 3) & 1) * 8) * 2;
    uint32_t bBase[6][2];
    #pragma unroll
    for (int g = 0; g < 6; g++) {
        int m = (g < 3) ? 0 : 1;
        int gc = g - m * 3;
        #pragma unroll
        for (int s = 0; s < 2; s++)
            bBase[g][s] = sb32 + SW_OFF +
                (uint32_t)((((s * 2 + m) * 192 + gc * 64 + fb) * WSTR) * 2) + boff;
    }

    int parity = 0;
    for (int tile = first; tile < ntiles; tile += gridDim.x) {
        int n0 = tile * 64;
        uint32_t cur = bufB[parity];

        int nxt = tile + gridDim.x;
        if (nxt < ntiles) {
            uint32_t dst = bufB[parity ^ 1];
            size_t go = (size_t)(nxt * 64 + srow) * HH + sseg * 8;
            CP_ASYNC16(dst + 0 * ACH + sdst, (const void*)(g_hn_hi + go));
            CP_ASYNC16(dst + 1 * ACH + sdst, (const void*)(g_hn_lo + go));
            CP_ASYNC16(dst + 2 * ACH + sdst, (const void*)(g_h_hi + go));
            CP_ASYNC16(dst + 3 * ACH + sdst, (const void*)(g_h_lo + go));
        }
        CP_COMMIT();

        uint32_t aB0 = cur + 0 * ACH + aoff;
        uint32_t aB1 = cur + 1 * ACH + aoff;
        uint32_t aB2 = cur + 2 * ACH + aoff;
        uint32_t aB3 = cur + 3 * ACH + aoff;

        float acc[12][4];
        #pragma unroll
        for (int i = 0; i < 12; i++) {
            acc[i][0] = 0.f; acc[i][1] = 0.f; acc[i][2] = 0.f; acc[i][3] = 0.f;
        }

        #pragma unroll
        for (int kc = 0; kc < 64; kc += 16) {
            uint32_t kb = kc * 2;
            uint32_t AnH[2][4], AnL[2][4], AhH[2][4], AhL[2][4];
            #pragma unroll
            for (int i = 0; i < 2; i++) {
                uint32_t off = (uint32_t)(i * 16 * ASTR * 2) + kb;
                LDSM4(AnH[i], aB0 + off);
                LDSM4(AnL[i], aB1 + off);
                LDSM4(AhH[i], aB2 + off);
                LDSM4(AhL[i], aB3 + off);
            }
            #pragma unroll
            for (int g = 0; g < 6; g++) {
                uint32_t Bh[2], Bl[2];
                LDSM2(Bh, bBase[g][0] + kb);
                LDSM2(Bl, bBase[g][1] + kb);
                #pragma unroll
                for (int i = 0; i < 2; i++) {
                    const uint32_t* ah = (g < 3) ? AnH[i] : AhH[i];
                    const uint32_t* al = (g < 3) ? AnL[i] : AhL[i];
                    MMA_BF16(acc[g * 2 + i], ah, Bh);
                    MMA_BF16(acc[g * 2 + i], ah, Bl);
                    MMA_BF16(acc[g * 2 + i], al, Bh);
                }
            }
        }

        // ---- register GRU epilogue + fused next-layer dots (R14 exact) ----
        #pragma unroll
        for (int i = 0; i < 2; i++) {
            #pragma unroll
            for (int hlf = 0; hlf < 2; hlf++) {
                int row = mh * 32 + i * 16 + gi + hlf * 8;
                int gn = n0 + row;
                float P1 = 0.f, P2 = 0.f;
                if (gn < n) {
                    int a = hlf * 2;
                    float2 hold = *(float2*)&g_h[(size_t)gn * HH + c0];
                    float ho[2];
                    #pragma unroll
                    for (int q = 0; q < 2; q++) {
                        float ir  = acc[0 * 2 + i][a + q] + bI[0][q];
                        float iz  = acc[1 * 2 + i][a + q] + bI[1][q];
                        float in_ = acc[2 * 2 + i][a + q] + bI[2][q];
                        float hr  = acc[3 * 2 + i][a + q] + bH[0][q];
                        float hz  = acc[4 * 2 + i][a + q] + bH[1][q];
                        float hn  = acc[5 * 2 + i][a + q] + bH[2][q];
                        float hv  = q ? hold.y : hold.x;
                        float r = sigm(ir + hr);
                        float z = sigm(iz + hz);
                        float nn_ = tanh_fast(fmaf(r, hn, in_));
                        ho[q] = fmaf(1.f - z, nn_, z * hv);
                    }
                    *(float2*)&g_h[(size_t)gn * HH + c0] = make_float2(ho[0], ho[1]);
                    __nv_bfloat16 h0 = __float2bfloat16(ho[0]);
                    __nv_bfloat16 h1 = __float2bfloat16(ho[1]);
                    __nv_bfloat16 l0 = __float2bfloat16(ho[0] - __bfloat162float(h0));
                    __nv_bfloat16 l1 = __float2bfloat16(ho[1] - __bfloat162float(h1));
                    *(uint32_t*)&g_h_hi[(size_t)gn * HH + c0] = pk2bf(h0, h1);
                    *(uint32_t*)&g_h_lo[(size_t)gn * HH + c0] = pk2bf(l0, l1);
                    P1 = ho[0] * we1a + ho[1] * we1b;
                    P2 = ho[0] * we2a + ho[1] * we2b;
                }
                P1 += __shfl_xor_sync(0xffffffffu, P1, 1);
                P1 += __shfl_xor_sync(0xffffffffu, P1, 2);
                P2 += __shfl_xor_sync(0xffffffffu, P2, 1);
                P2 += __shfl_xor_sync(0xffffffffu, P2, 2);
                if (tc == 0) {
                    sd[(0 * 64 + row) * 8 + wslot] = P1;
                    sd[(1 * 64 + row) * 8 + wslot] = P2;
                }
            }
        }
        __syncthreads();

        if (tid < 128) {
            int p = tid >> 6, row = tid & 63;
            int gn = n0 + row;
            if (gn < n) {
                const float* s = sd + (p * 64 + row) * 8;
                float v = ((s[0] + s[1]) + (s[2] + s[3])) + ((s[4] + s[5]) + (s[6] + s[7]));
                if (p == 0) g_a1[gn] = v; else g_a2[gn] = v;
            }
        }
        CP_WAIT0();
        __syncthreads();
        parity ^= 1;
    }
}

// ---------------- final edge predictor (2 edges/thread) ----------------
__global__ void k_pred(const int* __restrict__ src, const int* __restrict__ dst,
                       const float* __restrict__ bp, float* __restrict__ out, int e2) {
    int j = blockIdx.x * blockDim.x + threadIdx.x;
    if (j < e2) {
        int2 s = __ldg(&((const int2*)src)[j]);
        int2 d = __ldg(&((const int2*)dst)[j]);
        float b = bp[0];
        float2 o;
        o.x = __ldg(&g_a1[s.x]) + __ldg(&g_a2[d.x]) + b;
        o.y = __ldg(&g_a1[s.y]) + __ldg(&g_a2[d.y]) + b;
        ((float2*)out)[j] = o;
    }
}

// ---------------- launch ----------------
extern "C" void kernel_launch(void* const* d_in, const int* in_sizes, int n_in,
                              void* d_out, int out_size) {
    const float* feat = (const float*)d_in[0];
    const int*   src  = (const int*)d_in[1];
    const int*   dst  = (const int*)d_in[2];
    const float* Win  = (const float*)d_in[3];
    const float* bin  = (const float*)d_in[4];
    const float* We   = (const float*)d_in[5];
    const float* be   = (const float*)d_in[6];
    const float* Wih  = (const float*)d_in[7];
    const float* Whh  = (const float*)d_in[8];
    const float* bih  = (const float*)d_in[9];
    const float* bhh  = (const float*)d_in[10];
    const float* Wp   = (const float*)d_in[11];
    const float* bp   = (const float*)d_in[12];
    float* out = (float*)d_out;

    int n = in_sizes[0] / INF;   // 50000
    int e = in_sizes[1];         // 800000
    int nb = (n + 1023) / 1024;

    cudaFuncSetAttribute(k_gru, cudaFuncAttributeMaxDynamicSharedMemorySize, SMEM_BYTES);

    k_wsplit<<<(3 * 2 * 192 * 64 + 255) / 256, 256>>>(Wih, Whh);
    // CSR build (k_zero folded into k_scan1's self-zeroing)
    k_count<<<(e / 4 + 255) / 256, 256>>>((const int4*)dst, e / 4);
    k_scan1<<<nb, 1024>>>(n);
    k_scan3<<<nb, 1024>>>(nb, n);
    k_fill<<<(e + 255) / 256, 256>>>(src, dst, e);

    k_input<<<(n * HH + 255) / 256, 256>>>(feat, Win, bin, We, n);

    for (int l = 0; l < 3; l++) {
        k_w<<<(e / 2 + 255) / 256, 256>>>(be, e / 2);
        k_agg<<<(n + 7) / 8, 256>>>(n);
        const float* Wd = (l == 2) ? Wp : We;
        k_gru<<<148, 512, SMEM_BYTES>>>(l, bih + l * 192, bhh + l * 192, Wd, n);
    }

    k_pred<<<(e / 2 + 255) / 256, 256>>>(src, dst, bp, out, e / 2);
}